// round 7
// baseline (speedup 1.0000x reference)
#include <cuda_runtime.h>

#define NN 100000
#define EE 1600000
#define GG 512
#define LL 3
#define DIM 128
#define BN_EPS 1e-5f

// ---------------- scratch (static device globals; no allocation) ----------------
__device__ float4 g_A4[(size_t)NN * 32];       // activation / gather dst
__device__ float4 g_B4[(size_t)NN * 32];       // per-layer linear output (hl)
__device__ float  g_xs[(size_t)NN * LL * DIM]; // concat(xs) staging
__device__ float  g_deg[NN];
__device__ float  g_dinv[NN];
__device__ int    g_indeg[NN];
__device__ int    g_start[NN + 1];
__device__ int    g_cursor[NN];
__device__ int    g_csr_src[EE];
__device__ float  g_csr_w[EE];
__device__ float  g_sum[DIM];
__device__ float  g_sumsq[DIM];
__device__ float  g_scale[DIM];
__device__ float  g_shift[DIM];
__device__ int    g_cnt[GG];
__device__ int    g_off[GG + 1];

// ---------------- prep: degrees ----------------
__global__ void k_init() {
    int i = blockIdx.x * blockDim.x + threadIdx.x;
    if (i < NN) { g_deg[i] = 1.0f; g_indeg[i] = 0; }   // self-loop weight 1
    if (i < GG) g_cnt[i] = 0;
}

__global__ void k_deg(const int* __restrict__ ei, const float* __restrict__ ew) {
    int e = blockIdx.x * blockDim.x + threadIdx.x;
    if (e >= EE) return;
    int c = ei[EE + e];
    atomicAdd(&g_deg[c], ew[e]);
    atomicAdd(&g_indeg[c], 1);
}

__global__ void k_dinv() {
    int i = blockIdx.x * blockDim.x + threadIdx.x;
    if (i < NN) g_dinv[i] = rsqrtf(g_deg[i]);   // deg >= 1 always (self-loop)
}

// ---------------- single-block scan over in-degrees -> CSR starts ----------------
__global__ void k_scan_nodes() {
    __shared__ int part[1024];
    int t = threadIdx.x;
    const int CH = (NN + 1023) / 1024;
    int base = t * CH;
    int s = 0;
    for (int i = 0; i < CH; ++i) {
        int idx = base + i;
        if (idx < NN) s += g_indeg[idx];
    }
    part[t] = s;
    __syncthreads();
    for (int off = 1; off < 1024; off <<= 1) {
        int v = (t >= off) ? part[t - off] : 0;
        __syncthreads();
        part[t] += v;
        __syncthreads();
    }
    int run = part[t] - s;   // exclusive start for this chunk
    for (int i = 0; i < CH; ++i) {
        int idx = base + i;
        if (idx < NN) {
            g_start[idx]  = run;
            g_cursor[idx] = run;
            run += g_indeg[idx];
        }
    }
    if (t == 0) g_start[NN] = EE;
}

// ---------------- fill CSR (src + precomputed norm weight) ----------------
__global__ void k_fill(const int* __restrict__ ei, const float* __restrict__ ew) {
    int e = blockIdx.x * blockDim.x + threadIdx.x;
    if (e >= EE) return;
    int r = ei[e];
    int c = ei[EE + e];
    int slot = atomicAdd(&g_cursor[c], 1);
    g_csr_src[slot] = r;
    g_csr_w[slot]   = g_dinv[r] * ew[e] * g_dinv[c];
}

// ---------------- batch -> per-graph offsets (batch is sorted) ----------------
__global__ void k_count(const int* __restrict__ batch) {
    int i = blockIdx.x * blockDim.x + threadIdx.x;
    if (i < NN) atomicAdd(&g_cnt[batch[i]], 1);
}

__global__ void k_scan_graphs() {
    if (threadIdx.x == 0) {
        int acc = 0;
        g_off[0] = 0;
        for (int g = 0; g < GG; ++g) { acc += g_cnt[g]; g_off[g + 1] = acc; }
    }
}

// ---------------- GEMM: C[i][j] = sum_k A[i][k] * W[j][k] ----------------
// Static smem only (33.3 KB). 256 threads, 4 rows per warp = 32 rows/block.
// Two passes over output columns. A rows in registers (shfl-broadcast).
__global__ void k_gemm(const float* __restrict__ Ain, const float* __restrict__ W,
                       int mode, int n) {
    __shared__ float sW[128 * 65];   // sW[k*65 + jj], jj in [0,64)

    const float* A = mode ? (const float*)g_A4 : Ain;
    float*       C = mode ? (float*)g_B4 : (float*)g_A4;

    int tid  = threadIdx.x;
    int w    = tid >> 5;
    int lane = tid & 31;
    int row0 = blockIdx.x * 32 + w * 4;   // this warp's 4 rows

    for (int p = 0; p < 2; ++p) {
        for (int idx = tid; idx < 64 * 128; idx += 256) {
            int jj = idx >> 7, k = idx & 127;
            sW[k * 65 + jj] = W[(size_t)(p * 64 + jj) * 128 + k];
        }
        __syncthreads();

        float4 av[4];
#pragma unroll
        for (int r = 0; r < 4; ++r) {
            int gr = row0 + r;
            av[r] = (gr < n) ? ((const float4*)A)[(size_t)gr * 32 + lane]
                             : make_float4(0.f, 0.f, 0.f, 0.f);
        }

        float acc0[4] = {0.f, 0.f, 0.f, 0.f};
        float acc1[4] = {0.f, 0.f, 0.f, 0.f};

#pragma unroll 4
        for (int k = 0; k < 128; ++k) {
            float w0 = sW[k * 65 + lane];
            float w1 = sW[k * 65 + lane + 32];
            int src = k >> 2;
            int cmp = k & 3;
#pragma unroll
            for (int r = 0; r < 4; ++r) {
                float a;
                switch (cmp) {
                    case 0: a = __shfl_sync(0xffffffffu, av[r].x, src); break;
                    case 1: a = __shfl_sync(0xffffffffu, av[r].y, src); break;
                    case 2: a = __shfl_sync(0xffffffffu, av[r].z, src); break;
                    default: a = __shfl_sync(0xffffffffu, av[r].w, src); break;
                }
                acc0[r] = fmaf(a, w0, acc0[r]);
                acc1[r] = fmaf(a, w1, acc1[r]);
            }
        }

#pragma unroll
        for (int r = 0; r < 4; ++r) {
            int gr = row0 + r;
            if (gr < n) {
                float* cp = C + (size_t)gr * 128 + p * 64;
                cp[lane]      = acc0[r];
                cp[lane + 32] = acc1[r];
            }
        }
        __syncthreads();
    }
}

// ---------------- pull-gather: A[c] = selfw*B[c] + sum_in w*B[src] ----------------
__global__ void k_gather() {
    int node = blockIdx.x * (blockDim.x >> 5) + (threadIdx.x >> 5);
    if (node >= NN) return;
    int lane = threadIdx.x & 31;

    float d = g_dinv[node];
    float sw = d * d;
    float4 v = g_B4[(size_t)node * 32 + lane];
    float4 acc = make_float4(v.x * sw, v.y * sw, v.z * sw, v.w * sw);

    int s = g_start[node], e = g_start[node + 1];
    for (int j = s; j < e; ++j) {
        int r    = g_csr_src[j];
        float wt = g_csr_w[j];
        float4 u = g_B4[(size_t)r * 32 + lane];
        acc.x = fmaf(wt, u.x, acc.x);
        acc.y = fmaf(wt, u.y, acc.y);
        acc.z = fmaf(wt, u.z, acc.z);
        acc.w = fmaf(wt, u.w, acc.w);
    }
    g_A4[(size_t)node * 32 + lane] = acc;
}

// ---------------- BN ----------------
__global__ void k_zero_stats() {
    int c = threadIdx.x;
    g_sum[c] = 0.0f;
    g_sumsq[c] = 0.0f;
}

__global__ void k_bnstats(const float* __restrict__ bias) {
    int c = threadIdx.x;                       // 128 threads
    const float* Af = (const float*)g_A4;
    int chunk = (NN + gridDim.x - 1) / gridDim.x;
    int start = blockIdx.x * chunk;
    int end = min(start + chunk, NN);
    float bc = bias[c];
    float s = 0.0f, ss = 0.0f;
    for (int i = start; i < end; ++i) {
        float v = fmaxf(Af[(size_t)i * 128 + c] + bc, 0.0f);
        s += v;
        ss = fmaf(v, v, ss);
    }
    atomicAdd(&g_sum[c], s);
    atomicAdd(&g_sumsq[c], ss);
}

__global__ void k_bnfinal(const float* __restrict__ gamma, const float* __restrict__ beta) {
    int c = threadIdx.x;                       // 128 threads
    float mean = g_sum[c] * (1.0f / NN);
    float var  = fmaxf(g_sumsq[c] * (1.0f / NN) - mean * mean, 0.0f);
    float inv  = rsqrtf(var + BN_EPS);
    float sc   = gamma[c] * inv;
    g_scale[c] = sc;
    g_shift[c] = beta[c] - mean * sc;
}

// apply BN -> g_A (next layer input) and g_xs slice
__global__ void k_apply(const float* __restrict__ bias, int l) {
    long long t = (long long)blockIdx.x * blockDim.x + threadIdx.x;
    if (t >= (long long)NN * DIM) return;
    int c = (int)(t & 127);
    long long i = t >> 7;
    float* Af = (float*)g_A4;
    float v = fmaxf(Af[t] + bias[c], 0.0f);
    float y = fmaf(v, g_scale[c], g_shift[c]);
    Af[t] = y;
    g_xs[i * (LL * DIM) + (size_t)l * DIM + c] = y;
}

// ---------------- per-graph sum pooling (reads g_xs) ----------------
__global__ void k_pool(float* __restrict__ out) {
    int g = blockIdx.x;           // 512 blocks
    int c = threadIdx.x;          // 384 threads
    int s = g_off[g], e = g_off[g + 1];
    float acc = 0.0f;
    for (int i = s; i < e; ++i) acc += g_xs[(size_t)i * (LL * DIM) + c];
    out[(size_t)g * (LL * DIM) + c] = acc;
}

// ---------------- copy staged xs into d_out tail, bounded by out_size ----------------
__global__ void k_copy_xs(float* __restrict__ dst, long long count) {
    long long t = (long long)blockIdx.x * blockDim.x + threadIdx.x;
    if (t < count) dst[t] = g_xs[t];
}

// ---------------- launch (kernel launches ONLY — no host CUDA API calls) ----------------
extern "C" void kernel_launch(void* const* d_in, const int* in_sizes, int n_in,
                              void* d_out, int out_size) {
    const float* x     = (const float*)d_in[0];
    const int*   ei    = (const int*)d_in[1];     // int32 (JAX x64 disabled)
    const float* ew    = (const float*)d_in[2];
    const int*   batch = (const int*)d_in[3];     // int32
    const float* fc_w  = (const float*)d_in[4];
    const float* W     = (const float*)d_in[5];
    const float* b     = (const float*)d_in[6];
    const float* gamma = (const float*)d_in[7];
    const float* beta  = (const float*)d_in[8];

    float* out = (float*)d_out;                   // first GG*384: pooled

    const int T = 256;
    int nb_N  = (NN + T - 1) / T;
    int nb_E  = (EE + T - 1) / T;
    int nb_AP = (int)(((long long)NN * DIM + T - 1) / T);
    int nb_G  = (NN + 31) / 32;   // 32 rows per block
    int nb_GA = (NN + 7) / 8;     // warp per node

    // prep: degrees, CSR, batch offsets
    k_init<<<nb_N, T>>>();
    k_deg<<<nb_E, T>>>(ei, ew);
    k_dinv<<<nb_N, T>>>();
    k_scan_nodes<<<1, 1024>>>();
    k_fill<<<nb_E, T>>>(ei, ew);
    k_count<<<nb_N, T>>>(batch);
    k_scan_graphs<<<1, 32>>>();

    // h0 = x @ fc_w^T  -> g_A
    k_gemm<<<nb_G, T>>>(x, fc_w, 0, NN);

    for (int l = 0; l < LL; ++l) {
        k_gemm<<<nb_G, T>>>(nullptr, W + (size_t)l * DIM * DIM, 1, NN);
        k_gather<<<nb_GA, T>>>();
        k_zero_stats<<<1, 128>>>();
        k_bnstats<<<512, 128>>>(b + (size_t)l * DIM);
        k_bnfinal<<<1, 128>>>(gamma + (size_t)l * DIM, beta + (size_t)l * DIM);
        k_apply<<<nb_AP, T>>>(b + (size_t)l * DIM, l);
    }

    // pooled output at the head of d_out
    long long pool_elems = (long long)GG * LL * DIM;
    if ((long long)out_size >= pool_elems)
        k_pool<<<GG, LL * DIM>>>(out);

    // copy concat(xs) into whatever room remains in d_out
    long long rem = (long long)out_size - pool_elems;
    if (rem > 0) {
        long long cnt = rem < (long long)NN * LL * DIM ? rem : (long long)NN * LL * DIM;
        int nb_CP = (int)((cnt + T - 1) / T);
        k_copy_xs<<<nb_CP, T>>>(out + pool_elems, cnt);
    }
}

// round 9
// speedup vs baseline: 1.1875x; 1.1875x over previous
#include <cuda_runtime.h>

#define NN 100000
#define EE 1600000
#define GG 512
#define LL 3
#define DIM 128
#define BN_EPS 1e-5f
#define SCAN_B 1024
#define NBLK ((NN + SCAN_B - 1) / SCAN_B)   // 98

// ---------------- scratch (static device globals; no allocation) ----------------
__device__ float4 g_A4[(size_t)NN * 32];       // activation / gather dst
__device__ float4 g_B4[(size_t)NN * 32];       // per-layer linear output (hl)
__device__ float  g_xs[(size_t)NN * LL * DIM]; // concat(xs) staging (fallback only)
__device__ float  g_deg[NN];
__device__ float  g_dinv[NN];
__device__ int    g_indeg[NN];
__device__ int    g_start[NN + 1];
__device__ int    g_cursor[NN];
__device__ int2   g_csr[EE];                   // (src, weight bits)
__device__ int    g_part[NBLK];
__device__ float  g_sum[DIM];
__device__ float  g_sumsq[DIM];
__device__ float  g_scale[DIM];
__device__ float  g_shift[DIM];
__device__ int    g_cnt[GG];
__device__ int    g_off[GG + 1];

// ---------------- prep: degrees ----------------
__global__ void k_init() {
    int i = blockIdx.x * blockDim.x + threadIdx.x;
    if (i < NN) { g_deg[i] = 1.0f; g_indeg[i] = 0; }   // self-loop weight 1
    if (i < GG) g_cnt[i] = 0;
    if (i < DIM) { g_sum[i] = 0.0f; g_sumsq[i] = 0.0f; }
}

__global__ void k_deg(const int* __restrict__ ei, const float* __restrict__ ew) {
    int e = blockIdx.x * blockDim.x + threadIdx.x;
    if (e >= EE) return;
    int c = ei[EE + e];
    atomicAdd(&g_deg[c], ew[e]);
    atomicAdd(&g_indeg[c], 1);
}

__global__ void k_dinv() {
    int i = blockIdx.x * blockDim.x + threadIdx.x;
    if (i < NN) g_dinv[i] = rsqrtf(g_deg[i]);   // deg >= 1 (self-loop)
}

// ---------------- 3-phase parallel scan of in-degrees -> CSR starts ----------------
__global__ void k_scan_blk() {              // grid NBLK, block 1024
    __shared__ int sh[SCAN_B];
    int t = threadIdx.x;
    int i = blockIdx.x * SCAN_B + t;
    int v = (i < NN) ? g_indeg[i] : 0;
    sh[t] = v;
    __syncthreads();
    for (int off = 1; off < SCAN_B; off <<= 1) {
        int u = (t >= off) ? sh[t - off] : 0;
        __syncthreads();
        sh[t] += u;
        __syncthreads();
    }
    if (i < NN) g_start[i] = sh[t] - v;     // exclusive local prefix
    if (t == SCAN_B - 1) g_part[blockIdx.x] = sh[t];
}

__global__ void k_scan_mid() {              // 1 block
    if (threadIdx.x == 0) {
        int acc = 0;
        for (int b = 0; b < NBLK; ++b) { int u = g_part[b]; g_part[b] = acc; acc += u; }
    }
}

__global__ void k_scan_add() {              // grid-stride over nodes
    int i = blockIdx.x * blockDim.x + threadIdx.x;
    if (i < NN) {
        int s = g_start[i] + g_part[i >> 10];
        g_start[i]  = s;
        g_cursor[i] = s;
    }
    if (i == 0) g_start[NN] = EE;
}

// ---------------- fill CSR (src + precomputed norm weight, packed) ----------------
__global__ void k_fill(const int* __restrict__ ei, const float* __restrict__ ew) {
    int e = blockIdx.x * blockDim.x + threadIdx.x;
    if (e >= EE) return;
    int r = ei[e];
    int c = ei[EE + e];
    int slot = atomicAdd(&g_cursor[c], 1);
    float w = g_dinv[r] * ew[e] * g_dinv[c];
    g_csr[slot] = make_int2(r, __float_as_int(w));
}

// ---------------- batch -> per-graph offsets (batch is sorted) ----------------
__global__ void k_count(const int* __restrict__ batch) {
    int i = blockIdx.x * blockDim.x + threadIdx.x;
    if (i < NN) atomicAdd(&g_cnt[batch[i]], 1);
}

__global__ void k_scan_graphs() {
    if (threadIdx.x == 0) {
        int acc = 0;
        g_off[0] = 0;
        for (int g = 0; g < GG; ++g) { acc += g_cnt[g]; g_off[g + 1] = acc; }
    }
}

// ---------------- GEMM: C[i][j] = sum_k A[i][k] * W[j][k] ----------------
__global__ void k_gemm(const float* __restrict__ Ain, const float* __restrict__ W,
                       int mode, int n) {
    __shared__ float sW[128 * 65];   // sW[k*65 + jj], jj in [0,64)

    const float* A = mode ? (const float*)g_A4 : Ain;
    float*       C = mode ? (float*)g_B4 : (float*)g_A4;

    int tid  = threadIdx.x;
    int w    = tid >> 5;
    int lane = tid & 31;
    int row0 = blockIdx.x * 32 + w * 4;

    for (int p = 0; p < 2; ++p) {
        for (int idx = tid; idx < 64 * 128; idx += 256) {
            int jj = idx >> 7, k = idx & 127;
            sW[k * 65 + jj] = W[(size_t)(p * 64 + jj) * 128 + k];
        }
        __syncthreads();

        float4 av[4];
#pragma unroll
        for (int r = 0; r < 4; ++r) {
            int gr = row0 + r;
            av[r] = (gr < n) ? ((const float4*)A)[(size_t)gr * 32 + lane]
                             : make_float4(0.f, 0.f, 0.f, 0.f);
        }

        float acc0[4] = {0.f, 0.f, 0.f, 0.f};
        float acc1[4] = {0.f, 0.f, 0.f, 0.f};

#pragma unroll 4
        for (int k = 0; k < 128; ++k) {
            float w0 = sW[k * 65 + lane];
            float w1 = sW[k * 65 + lane + 32];
            int src = k >> 2;
            int cmp = k & 3;
#pragma unroll
            for (int r = 0; r < 4; ++r) {
                float a;
                switch (cmp) {
                    case 0: a = __shfl_sync(0xffffffffu, av[r].x, src); break;
                    case 1: a = __shfl_sync(0xffffffffu, av[r].y, src); break;
                    case 2: a = __shfl_sync(0xffffffffu, av[r].z, src); break;
                    default: a = __shfl_sync(0xffffffffu, av[r].w, src); break;
                }
                acc0[r] = fmaf(a, w0, acc0[r]);
                acc1[r] = fmaf(a, w1, acc1[r]);
            }
        }

#pragma unroll
        for (int r = 0; r < 4; ++r) {
            int gr = row0 + r;
            if (gr < n) {
                float* cp = C + (size_t)gr * 128 + p * 64;
                cp[lane]      = acc0[r];
                cp[lane + 32] = acc1[r];
            }
        }
        __syncthreads();
    }
}

// ---------------- pull-gather + bias + relu: A[c] = relu(selfw*B[c] + sum w*B[src] + b) ----------------
__global__ void k_gather(const float* __restrict__ bias) {
    int node = blockIdx.x * (blockDim.x >> 5) + (threadIdx.x >> 5);
    if (node >= NN) return;
    int lane = threadIdx.x & 31;

    float d = g_dinv[node];
    float sw = d * d;
    float4 v = g_B4[(size_t)node * 32 + lane];
    float4 acc = make_float4(v.x * sw, v.y * sw, v.z * sw, v.w * sw);

    int s = g_start[node], e = g_start[node + 1];
    int j = s;
    for (; j + 1 < e; j += 2) {             // 2-deep for MLP
        int2 c0 = g_csr[j];
        int2 c1 = g_csr[j + 1];
        float4 u0 = g_B4[(size_t)c0.x * 32 + lane];
        float4 u1 = g_B4[(size_t)c1.x * 32 + lane];
        float w0 = __int_as_float(c0.y);
        float w1 = __int_as_float(c1.y);
        acc.x = fmaf(w0, u0.x, acc.x); acc.y = fmaf(w0, u0.y, acc.y);
        acc.z = fmaf(w0, u0.z, acc.z); acc.w = fmaf(w0, u0.w, acc.w);
        acc.x = fmaf(w1, u1.x, acc.x); acc.y = fmaf(w1, u1.y, acc.y);
        acc.z = fmaf(w1, u1.z, acc.z); acc.w = fmaf(w1, u1.w, acc.w);
    }
    if (j < e) {
        int2 c0 = g_csr[j];
        float4 u0 = g_B4[(size_t)c0.x * 32 + lane];
        float w0 = __int_as_float(c0.y);
        acc.x = fmaf(w0, u0.x, acc.x); acc.y = fmaf(w0, u0.y, acc.y);
        acc.z = fmaf(w0, u0.z, acc.z); acc.w = fmaf(w0, u0.w, acc.w);
    }

    float4 bc = ((const float4*)bias)[lane];
    acc.x = fmaxf(acc.x + bc.x, 0.0f);
    acc.y = fmaxf(acc.y + bc.y, 0.0f);
    acc.z = fmaxf(acc.z + bc.z, 0.0f);
    acc.w = fmaxf(acc.w + bc.w, 0.0f);
    g_A4[(size_t)node * 32 + lane] = acc;
}

// ---------------- BN stats (A already has bias+relu applied) ----------------
__global__ void k_bnstats() {
    int c = threadIdx.x;                       // 128 threads
    const float* Af = (const float*)g_A4;
    int chunk = (NN + gridDim.x - 1) / gridDim.x;
    int start = blockIdx.x * chunk;
    int end = min(start + chunk, NN);
    float s = 0.0f, ss = 0.0f;
    for (int i = start; i < end; ++i) {
        float v = Af[(size_t)i * 128 + c];
        s += v;
        ss = fmaf(v, v, ss);
    }
    atomicAdd(&g_sum[c], s);
    atomicAdd(&g_sumsq[c], ss);
}

__global__ void k_bnfinal(const float* __restrict__ gamma, const float* __restrict__ beta) {
    int c = threadIdx.x;                       // 128 threads
    float mean = g_sum[c] * (1.0f / NN);
    float var  = fmaxf(g_sumsq[c] * (1.0f / NN) - mean * mean, 0.0f);
    float inv  = rsqrtf(var + BN_EPS);
    float sc   = gamma[c] * inv;
    g_scale[c] = sc;
    g_shift[c] = beta[c] - mean * sc;
}

// apply BN -> A (next layer input) and xs slice; zero stats for next layer
__global__ void k_apply(float* __restrict__ xs_dst, int l) {
    long long t = (long long)blockIdx.x * blockDim.x + threadIdx.x;
    if (t < DIM) { g_sum[t] = 0.0f; g_sumsq[t] = 0.0f; }
    if (t >= (long long)NN * DIM) return;
    int c = (int)(t & 127);
    long long i = t >> 7;
    float* Af = (float*)g_A4;
    float y = fmaf(Af[t], g_scale[c], g_shift[c]);
    Af[t] = y;
    xs_dst[i * (LL * DIM) + (size_t)l * DIM + c] = y;
}

// ---------------- per-graph sum pooling ----------------
__global__ void k_pool(const float* __restrict__ xs, float* __restrict__ out) {
    int g = blockIdx.x;           // 512 blocks
    int c = threadIdx.x;          // 384 threads
    int s = g_off[g], e = g_off[g + 1];
    float acc = 0.0f;
    for (int i = s; i < e; ++i) acc += xs[(size_t)i * (LL * DIM) + c];
    out[(size_t)g * (LL * DIM) + c] = acc;
}

// ---------------- fallback copy (only if d_out can't hold full xs) ----------------
__global__ void k_copy_xs(float* __restrict__ dst, long long count) {
    long long t = (long long)blockIdx.x * blockDim.x + threadIdx.x;
    if (t < count) dst[t] = g_xs[t];
}

// ---------------- launch (kernel launches ONLY) ----------------
extern "C" void kernel_launch(void* const* d_in, const int* in_sizes, int n_in,
                              void* d_out, int out_size) {
    const float* x     = (const float*)d_in[0];
    const int*   ei    = (const int*)d_in[1];     // int32
    const float* ew    = (const float*)d_in[2];
    const int*   batch = (const int*)d_in[3];     // int32
    const float* fc_w  = (const float*)d_in[4];
    const float* W     = (const float*)d_in[5];
    const float* b     = (const float*)d_in[6];
    const float* gamma = (const float*)d_in[7];
    const float* beta  = (const float*)d_in[8];

    float* out = (float*)d_out;

    const long long pool_elems = (long long)GG * LL * DIM;
    const long long xs_elems   = (long long)NN * LL * DIM;
    long long rem = (long long)out_size - pool_elems;
    bool direct = (rem >= xs_elems);

    // device-global symbol address can't be taken on host without an API call,
    // so select destination via a flag: k_apply gets out-tail when direct.
    float* xs_out_tail = out + pool_elems;

    const int T = 256;
    int nb_N  = (NN + T - 1) / T;
    int nb_E  = (EE + T - 1) / T;
    int nb_AP = (int)(((long long)NN * DIM + T - 1) / T);
    int nb_G  = (NN + 31) / 32;
    int nb_GA = (NN + 7) / 8;

    // prep
    k_init<<<nb_N, T>>>();
    k_deg<<<nb_E, T>>>(ei, ew);
    k_dinv<<<nb_N, T>>>();
    k_scan_blk<<<NBLK, SCAN_B>>>();
    k_scan_mid<<<1, 32>>>();
    k_scan_add<<<nb_N, T>>>();
    k_fill<<<nb_E, T>>>(ei, ew);
    k_count<<<nb_N, T>>>(batch);
    k_scan_graphs<<<1, 32>>>();

    // h0 = x @ fc_w^T  -> g_A
    k_gemm<<<nb_G, T>>>(x, fc_w, 0, NN);

    for (int l = 0; l < LL; ++l) {
        k_gemm<<<nb_G, T>>>(nullptr, W + (size_t)l * DIM * DIM, 1, NN);
        k_gather<<<nb_GA, T>>>(b + (size_t)l * DIM);
        k_bnstats<<<512, 128>>>();
        k_bnfinal<<<1, 128>>>(gamma + (size_t)l * DIM, beta + (size_t)l * DIM);
        if (direct)
            k_apply<<<nb_AP, T>>>(xs_out_tail, l);
        else
            k_apply<<<nb_AP, T>>>(g_xs, l);       // device-symbol as arg is valid in device code context
    }

    if ((long long)out_size >= pool_elems) {
        if (direct)
            k_pool<<<GG, LL * DIM>>>(xs_out_tail, out);
        else
            k_pool<<<GG, LL * DIM>>>(g_xs, out);
    }

    // partial-room fallback
    if (!direct && rem > 0) {
        long long cnt = rem < xs_elems ? rem : xs_elems;
        int nb_CP = (int)((cnt + T - 1) / T);
        k_copy_xs<<<nb_CP, T>>>(out + pool_elems, cnt);
    }
}

// round 10
// speedup vs baseline: 1.2639x; 1.0643x over previous
#include <cuda_runtime.h>

#define NN 100000
#define EE 1600000
#define GG 512
#define LL 3
#define DIM 128
#define BN_EPS 1e-5f
#define SCAN_B 1024
#define NBLK ((NN + SCAN_B - 1) / SCAN_B)   // 98

// ---------------- scratch (static device globals; no allocation) ----------------
__device__ float4 g_A4[(size_t)NN * 32];       // activation (pre-BN after gather)
__device__ float4 g_B4[(size_t)NN * 32];       // per-layer linear output (hl)
__device__ float  g_xs[(size_t)NN * LL * DIM]; // fallback staging
__device__ float  g_deg[NN];
__device__ float  g_dinv[NN];
__device__ int    g_indeg[NN];
__device__ int    g_start[NN + 1];
__device__ int    g_cursor[NN];
__device__ int2   g_csr[EE];                   // (src, weight bits)
__device__ int    g_part[NBLK];
__device__ float  g_sum[DIM];
__device__ float  g_sumsq[DIM];
__device__ float  g_scale[DIM];
__device__ float  g_shift[DIM];
__device__ int    g_cnt[GG];
__device__ int    g_off[GG + 1];

// ---------------- prep ----------------
__global__ void k_init() {
    int i = blockIdx.x * blockDim.x + threadIdx.x;
    if (i < NN) { g_deg[i] = 1.0f; g_indeg[i] = 0; }
    if (i < GG) g_cnt[i] = 0;
    if (i < DIM) { g_sum[i] = 0.0f; g_sumsq[i] = 0.0f; }
}

__global__ void k_deg(const int* __restrict__ ei, const float* __restrict__ ew) {
    int e = blockIdx.x * blockDim.x + threadIdx.x;
    if (e >= EE) return;
    int c = ei[EE + e];
    atomicAdd(&g_deg[c], ew[e]);
    atomicAdd(&g_indeg[c], 1);
}

__global__ void k_dinv() {
    int i = blockIdx.x * blockDim.x + threadIdx.x;
    if (i < NN) g_dinv[i] = rsqrtf(g_deg[i]);
}

__global__ void k_scan_blk() {
    __shared__ int sh[SCAN_B];
    int t = threadIdx.x;
    int i = blockIdx.x * SCAN_B + t;
    int v = (i < NN) ? g_indeg[i] : 0;
    sh[t] = v;
    __syncthreads();
    for (int off = 1; off < SCAN_B; off <<= 1) {
        int u = (t >= off) ? sh[t - off] : 0;
        __syncthreads();
        sh[t] += u;
        __syncthreads();
    }
    if (i < NN) g_start[i] = sh[t] - v;
    if (t == SCAN_B - 1) g_part[blockIdx.x] = sh[t];
}

__global__ void k_scan_mid() {
    if (threadIdx.x == 0) {
        int acc = 0;
        for (int b = 0; b < NBLK; ++b) { int u = g_part[b]; g_part[b] = acc; acc += u; }
    }
}

__global__ void k_scan_add() {
    int i = blockIdx.x * blockDim.x + threadIdx.x;
    if (i < NN) {
        int s = g_start[i] + g_part[i >> 10];
        g_start[i]  = s;
        g_cursor[i] = s;
    }
    if (i == 0) g_start[NN] = EE;
}

__global__ void k_fill(const int* __restrict__ ei, const float* __restrict__ ew) {
    int e = blockIdx.x * blockDim.x + threadIdx.x;
    if (e >= EE) return;
    int r = ei[e];
    int c = ei[EE + e];
    int slot = atomicAdd(&g_cursor[c], 1);
    float w = g_dinv[r] * ew[e] * g_dinv[c];
    g_csr[slot] = make_int2(r, __float_as_int(w));
}

__global__ void k_count(const int* __restrict__ batch) {
    int i = blockIdx.x * blockDim.x + threadIdx.x;
    if (i < NN) atomicAdd(&g_cnt[batch[i]], 1);
}

__global__ void k_scan_graphs() {
    if (threadIdx.x == 0) {
        int acc = 0;
        g_off[0] = 0;
        for (int g = 0; g < GG; ++g) { acc += g_cnt[g]; g_off[g + 1] = acc; }
    }
}

// ---------------- tf32 tensor-core GEMM: C[i][j] = sum_k A'[i][k] * W[j][k] ----------------
// A' = affine ? A*scale+shift (per column) : A. 128 threads (4 warps), 64 rows/block.
// A tile in smem (row stride 132 -> conflict-free frag loads). B frags LDG'd from W (L1-resident).
__device__ __forceinline__ unsigned f2tf(float f) {
    unsigned u;
    asm("cvt.rna.tf32.f32 %0, %1;" : "=r"(u) : "f"(f));
    return u;
}

__global__ void __launch_bounds__(128)
k_gemm_tc(const float* __restrict__ Ain, const float* __restrict__ W,
          int mode, int affine, int n) {
    __shared__ float sA[64 * 132];   // 33792 B

    const float* A = mode ? (const float*)g_A4 : Ain;
    float*       C = mode ? (float*)g_B4 : (float*)g_A4;

    int tid  = threadIdx.x;
    int warp = tid >> 5;
    int lane = tid & 31;
    int row0 = blockIdx.x * 64;

    // load A tile (affine applied at load)
    for (int idx = tid; idx < 64 * 32; idx += 128) {
        int r = idx >> 5, c4 = idx & 31;
        int gr = row0 + r;
        float4 v = (gr < n) ? ((const float4*)A)[(size_t)gr * 32 + c4]
                            : make_float4(0.f, 0.f, 0.f, 0.f);
        if (affine) {
            float4 sc = ((const float4*)g_scale)[c4];
            float4 sh = ((const float4*)g_shift)[c4];
            v.x = fmaf(v.x, sc.x, sh.x);
            v.y = fmaf(v.y, sc.y, sh.y);
            v.z = fmaf(v.z, sc.z, sh.z);
            v.w = fmaf(v.w, sc.w, sh.w);
        }
        *(float4*)&sA[(size_t)r * 132 + c4 * 4] = v;
    }
    __syncthreads();

    float d[16][4];
#pragma unroll
    for (int nt = 0; nt < 16; ++nt)
#pragma unroll
        for (int i = 0; i < 4; ++i) d[nt][i] = 0.0f;

    int rbase = warp * 16;
    int ar = rbase + (lane >> 2);
    const float* wbase = W + (size_t)(lane >> 2) * 128 + (lane & 3);

    for (int ks = 0; ks < 16; ++ks) {
        int k0 = ks * 8;
        unsigned a0 = f2tf(sA[ar * 132 + k0 + (lane & 3)]);
        unsigned a1 = f2tf(sA[(ar + 8) * 132 + k0 + (lane & 3)]);
        unsigned a2 = f2tf(sA[ar * 132 + k0 + (lane & 3) + 4]);
        unsigned a3 = f2tf(sA[(ar + 8) * 132 + k0 + (lane & 3) + 4]);
#pragma unroll
        for (int nt = 0; nt < 16; ++nt) {
            const float* wp = wbase + (size_t)nt * 8 * 128 + k0;
            unsigned b0 = f2tf(__ldg(wp));
            unsigned b1 = f2tf(__ldg(wp + 4));
            asm("mma.sync.aligned.m16n8k8.row.col.f32.tf32.tf32.f32 "
                "{%0,%1,%2,%3}, {%4,%5,%6,%7}, {%8,%9}, {%0,%1,%2,%3};"
                : "+f"(d[nt][0]), "+f"(d[nt][1]), "+f"(d[nt][2]), "+f"(d[nt][3])
                : "r"(a0), "r"(a1), "r"(a2), "r"(a3), "r"(b0), "r"(b1));
        }
    }

    int r0 = row0 + rbase + (lane >> 2);
#pragma unroll
    for (int nt = 0; nt < 16; ++nt) {
        int col = nt * 8 + 2 * (lane & 3);
        if (r0 < n)
            *(float2*)&C[(size_t)r0 * 128 + col] = make_float2(d[nt][0], d[nt][1]);
        if (r0 + 8 < n)
            *(float2*)&C[(size_t)(r0 + 8) * 128 + col] = make_float2(d[nt][2], d[nt][3]);
    }
}

// ---------------- gather + bias + relu + fused BN stats ----------------
// 512 threads = 16 warps = 16 nodes per block.
__global__ void __launch_bounds__(512)
k_gather(const float* __restrict__ bias) {
    __shared__ float ssum[DIM], ssq[DIM];
    int tid = threadIdx.x;
    if (tid < DIM) { ssum[tid] = 0.0f; ssq[tid] = 0.0f; }
    __syncthreads();

    int node = blockIdx.x * 16 + (tid >> 5);
    int lane = tid & 31;

    if (node < NN) {
        float dv = g_dinv[node];
        float sw = dv * dv;
        float4 v = g_B4[(size_t)node * 32 + lane];
        float4 acc = make_float4(v.x * sw, v.y * sw, v.z * sw, v.w * sw);

        int s = g_start[node], e = g_start[node + 1];
        int j = s;
        for (; j + 1 < e; j += 2) {
            int2 c0 = g_csr[j];
            int2 c1 = g_csr[j + 1];
            float4 u0 = g_B4[(size_t)c0.x * 32 + lane];
            float4 u1 = g_B4[(size_t)c1.x * 32 + lane];
            float w0 = __int_as_float(c0.y);
            float w1 = __int_as_float(c1.y);
            acc.x = fmaf(w0, u0.x, acc.x); acc.y = fmaf(w0, u0.y, acc.y);
            acc.z = fmaf(w0, u0.z, acc.z); acc.w = fmaf(w0, u0.w, acc.w);
            acc.x = fmaf(w1, u1.x, acc.x); acc.y = fmaf(w1, u1.y, acc.y);
            acc.z = fmaf(w1, u1.z, acc.z); acc.w = fmaf(w1, u1.w, acc.w);
        }
        if (j < e) {
            int2 c0 = g_csr[j];
            float4 u0 = g_B4[(size_t)c0.x * 32 + lane];
            float w0 = __int_as_float(c0.y);
            acc.x = fmaf(w0, u0.x, acc.x); acc.y = fmaf(w0, u0.y, acc.y);
            acc.z = fmaf(w0, u0.z, acc.z); acc.w = fmaf(w0, u0.w, acc.w);
        }

        float4 bc = ((const float4*)bias)[lane];
        acc.x = fmaxf(acc.x + bc.x, 0.0f);
        acc.y = fmaxf(acc.y + bc.y, 0.0f);
        acc.z = fmaxf(acc.z + bc.z, 0.0f);
        acc.w = fmaxf(acc.w + bc.w, 0.0f);
        g_A4[(size_t)node * 32 + lane] = acc;

        int cb = lane * 4;
        atomicAdd(&ssum[cb + 0], acc.x); atomicAdd(&ssq[cb + 0], acc.x * acc.x);
        atomicAdd(&ssum[cb + 1], acc.y); atomicAdd(&ssq[cb + 1], acc.y * acc.y);
        atomicAdd(&ssum[cb + 2], acc.z); atomicAdd(&ssq[cb + 2], acc.z * acc.z);
        atomicAdd(&ssum[cb + 3], acc.w); atomicAdd(&ssq[cb + 3], acc.w * acc.w);
    }
    __syncthreads();
    if (tid < DIM) {
        atomicAdd(&g_sum[tid], ssum[tid]);
        atomicAdd(&g_sumsq[tid], ssq[tid]);
    }
}

__global__ void k_bnfinal(const float* __restrict__ gamma, const float* __restrict__ beta) {
    int c = threadIdx.x;
    float mean = g_sum[c] * (1.0f / NN);
    float var  = fmaxf(g_sumsq[c] * (1.0f / NN) - mean * mean, 0.0f);
    float inv  = rsqrtf(var + BN_EPS);
    float sc   = gamma[c] * inv;
    g_scale[c] = sc;
    g_shift[c] = beta[c] - mean * sc;
}

// BN-apply -> xs slice only (g_A stays pre-BN; next GEMM applies affine at load).
// Also zeroes stats for the next layer's gather.
__global__ void k_apply(float* __restrict__ xs_dst, int l) {
    long long t = (long long)blockIdx.x * blockDim.x + threadIdx.x;
    if (t < DIM) { g_sum[t] = 0.0f; g_sumsq[t] = 0.0f; }
    if (t >= (long long)NN * DIM) return;
    int c = (int)(t & 127);
    long long i = t >> 7;
    const float* Af = (const float*)g_A4;
    float y = fmaf(Af[t], g_scale[c], g_shift[c]);
    xs_dst[i * (LL * DIM) + (size_t)l * DIM + c] = y;
}

__global__ void k_pool(const float* __restrict__ xs, float* __restrict__ out) {
    int g = blockIdx.x;
    int c = threadIdx.x;
    int s = g_off[g], e = g_off[g + 1];
    float acc = 0.0f;
    for (int i = s; i < e; ++i) acc += xs[(size_t)i * (LL * DIM) + c];
    out[(size_t)g * (LL * DIM) + c] = acc;
}

__global__ void k_copy_xs(float* __restrict__ dst, long long count) {
    long long t = (long long)blockIdx.x * blockDim.x + threadIdx.x;
    if (t < count) dst[t] = g_xs[t];
}

// ---------------- launch (kernel launches ONLY) ----------------
extern "C" void kernel_launch(void* const* d_in, const int* in_sizes, int n_in,
                              void* d_out, int out_size) {
    const float* x     = (const float*)d_in[0];
    const int*   ei    = (const int*)d_in[1];
    const float* ew    = (const float*)d_in[2];
    const int*   batch = (const int*)d_in[3];
    const float* fc_w  = (const float*)d_in[4];
    const float* W     = (const float*)d_in[5];
    const float* b     = (const float*)d_in[6];
    const float* gamma = (const float*)d_in[7];
    const float* beta  = (const float*)d_in[8];

    float* out = (float*)d_out;

    const long long pool_elems = (long long)GG * LL * DIM;
    const long long xs_elems   = (long long)NN * LL * DIM;
    long long rem = (long long)out_size - pool_elems;
    bool direct = (rem >= xs_elems);
    float* xs_out_tail = out + pool_elems;

    const int T = 256;
    int nb_N  = (NN + T - 1) / T;
    int nb_E  = (EE + T - 1) / T;
    int nb_AP = (int)(((long long)NN * DIM + T - 1) / T);
    int nb_G  = (NN + 63) / 64;    // tc gemm: 64 rows/block
    int nb_GA = (NN + 15) / 16;    // gather: 16 nodes/block

    // prep
    k_init<<<nb_N, T>>>();
    k_deg<<<nb_E, T>>>(ei, ew);
    k_dinv<<<nb_N, T>>>();
    k_scan_blk<<<NBLK, SCAN_B>>>();
    k_scan_mid<<<1, 32>>>();
    k_scan_add<<<nb_N, T>>>();
    k_fill<<<nb_E, T>>>(ei, ew);
    k_count<<<nb_N, T>>>(batch);
    k_scan_graphs<<<1, 32>>>();

    // h0 = x @ fc_w^T -> g_A (no affine)
    k_gemm_tc<<<nb_G, 128>>>(x, fc_w, 0, 0, NN);

    for (int l = 0; l < LL; ++l) {
        // hl = A' @ W[l]^T -> g_B  (A' = BN-affine of g_A for l>=1)
        k_gemm_tc<<<nb_G, 128>>>(nullptr, W + (size_t)l * DIM * DIM, 1, l > 0 ? 1 : 0, NN);
        k_gather<<<nb_GA, 512>>>(b + (size_t)l * DIM);
        k_bnfinal<<<1, 128>>>(gamma + (size_t)l * DIM, beta + (size_t)l * DIM);
        if (direct)
            k_apply<<<nb_AP, T>>>(xs_out_tail, l);
        else
            k_apply<<<nb_AP, T>>>(g_xs, l);
    }

    if ((long long)out_size >= pool_elems) {
        if (direct)
            k_pool<<<GG, LL * DIM>>>(xs_out_tail, out);
        else
            k_pool<<<GG, LL * DIM>>>(g_xs, out);
    }

    if (!direct && rem > 0) {
        long long cnt = rem < xs_elems ? rem : xs_elems;
        int nb_CP = (int)((cnt + T - 1) / T);
        k_copy_xs<<<nb_CP, T>>>(out + pool_elems, cnt);
    }
}

// round 12
// speedup vs baseline: 1.5862x; 1.2550x over previous
#include <cuda_runtime.h>

#define NN 100000
#define EE 1600000
#define GG 512
#define LL 3
#define DIM 128
#define BN_EPS 1e-5f
#define SCAN_B 1024
#define NBLK ((NN + SCAN_B - 1) / SCAN_B)   // 98

// ---------------- scratch (static device globals; no allocation) ----------------
__device__ float4 g_A4[(size_t)NN * 32];       // activation (pre-BN after gather)
__device__ float4 g_B4[(size_t)NN * 32];       // per-layer linear output (hl)
__device__ float  g_xs[(size_t)NN * LL * DIM]; // fallback staging
__device__ float  g_deg[NN];
__device__ float  g_dinv[NN];
__device__ int    g_indeg[NN];
__device__ int    g_start[NN + 1];
__device__ int    g_cursor[NN];
__device__ int2   g_csr[EE];                   // (src, weight bits)
__device__ int    g_part[NBLK];
__device__ float  g_sum[DIM];
__device__ float  g_sumsq[DIM];
__device__ float  g_scale[DIM];
__device__ float  g_shift[DIM];
__device__ int    g_cnt[GG];
__device__ int    g_off[GG + 1];

// ---------------- prep ----------------
__global__ void k_init() {
    int i = blockIdx.x * blockDim.x + threadIdx.x;
    if (i < NN) { g_deg[i] = 1.0f; g_indeg[i] = 0; }
    if (i < GG) g_cnt[i] = 0;
    if (i < DIM) { g_sum[i] = 0.0f; g_sumsq[i] = 0.0f; }
}

__global__ void k_deg(const int* __restrict__ ei, const float* __restrict__ ew) {
    int e = blockIdx.x * blockDim.x + threadIdx.x;
    if (e >= EE) return;
    int c = ei[EE + e];
    atomicAdd(&g_deg[c], ew[e]);
    atomicAdd(&g_indeg[c], 1);
}

__global__ void k_dinv() {
    int i = blockIdx.x * blockDim.x + threadIdx.x;
    if (i < NN) g_dinv[i] = rsqrtf(g_deg[i]);
}

__global__ void k_scan_blk() {
    __shared__ int sh[SCAN_B];
    int t = threadIdx.x;
    int i = blockIdx.x * SCAN_B + t;
    int v = (i < NN) ? g_indeg[i] : 0;
    sh[t] = v;
    __syncthreads();
    for (int off = 1; off < SCAN_B; off <<= 1) {
        int u = (t >= off) ? sh[t - off] : 0;
        __syncthreads();
        sh[t] += u;
        __syncthreads();
    }
    if (i < NN) g_start[i] = sh[t] - v;
    if (t == SCAN_B - 1) g_part[blockIdx.x] = sh[t];
}

__global__ void k_scan_mid() {
    if (threadIdx.x == 0) {
        int acc = 0;
        for (int b = 0; b < NBLK; ++b) { int u = g_part[b]; g_part[b] = acc; acc += u; }
    }
}

__global__ void k_scan_add() {
    int i = blockIdx.x * blockDim.x + threadIdx.x;
    if (i < NN) {
        int s = g_start[i] + g_part[i >> 10];
        g_start[i]  = s;
        g_cursor[i] = s;
    }
    if (i == 0) g_start[NN] = EE;
}

__global__ void k_fill(const int* __restrict__ ei, const float* __restrict__ ew) {
    int e = blockIdx.x * blockDim.x + threadIdx.x;
    if (e >= EE) return;
    int r = ei[e];
    int c = ei[EE + e];
    int slot = atomicAdd(&g_cursor[c], 1);
    float w = g_dinv[r] * ew[e] * g_dinv[c];
    g_csr[slot] = make_int2(r, __float_as_int(w));
}

__global__ void k_count(const int* __restrict__ batch) {
    int i = blockIdx.x * blockDim.x + threadIdx.x;
    if (i < NN) atomicAdd(&g_cnt[batch[i]], 1);
}

__global__ void k_scan_graphs() {
    if (threadIdx.x == 0) {
        int acc = 0;
        g_off[0] = 0;
        for (int g = 0; g < GG; ++g) { acc += g_cnt[g]; g_off[g + 1] = acc; }
    }
}

// ---------------- tf32 tensor-core GEMM: C[i][j] = sum_k A'[i][k] * W[j][k] ----------------
// 128 threads (4 warps), 64 rows/block. A tile + W chunks staged in smem as
// pre-converted tf32 bits; double-buffered W chunks; inner loop = LDS + MMA only.
__device__ __forceinline__ unsigned f2tf(float f) {
    unsigned u;
    asm("cvt.rna.tf32.f32 %0, %1;" : "=r"(u) : "f"(f));
    return u;
}

__global__ void __launch_bounds__(128)
k_gemm_tc(const float* __restrict__ Ain, const float* __restrict__ W,
          int mode, int affine, int n) {
    __shared__ unsigned sA[64 * 132];      // 33792 B, row stride 132 (a-frag conflict-free)
    __shared__ unsigned sB[2][8 * 136];    // 8704 B, row stride 136 (b-frag conflict-free)

    const float* A = mode ? (const float*)g_A4 : Ain;
    float*       C = mode ? (float*)g_B4 : (float*)g_A4;

    int tid  = threadIdx.x;
    int warp = tid >> 5;
    int lane = tid & 31;
    int row0 = blockIdx.x * 64;

    // load A tile (affine applied, converted to tf32 bits)
    for (int idx = tid; idx < 64 * 32; idx += 128) {
        int r = idx >> 5, c4 = idx & 31;
        int gr = row0 + r;
        float4 v = (gr < n) ? ((const float4*)A)[(size_t)gr * 32 + c4]
                            : make_float4(0.f, 0.f, 0.f, 0.f);
        if (affine) {
            float4 sc = ((const float4*)g_scale)[c4];
            float4 sh = ((const float4*)g_shift)[c4];
            v.x = fmaf(v.x, sc.x, sh.x);
            v.y = fmaf(v.y, sc.y, sh.y);
            v.z = fmaf(v.z, sc.z, sh.z);
            v.w = fmaf(v.w, sc.w, sh.w);
        }
        uint4 p = make_uint4(f2tf(v.x), f2tf(v.y), f2tf(v.z), f2tf(v.w));
        *(uint4*)&sA[(size_t)r * 132 + c4 * 4] = p;
    }

    // preload W chunk 0 (coalesced: thread tid owns output row n=tid, 8 k-floats)
    {
        const float4* wr = (const float4*)(W + (size_t)tid * 128);
        float4 w0 = wr[0], w1 = wr[1];
        sB[0][0 * 136 + tid] = f2tf(w0.x);
        sB[0][1 * 136 + tid] = f2tf(w0.y);
        sB[0][2 * 136 + tid] = f2tf(w0.z);
        sB[0][3 * 136 + tid] = f2tf(w0.w);
        sB[0][4 * 136 + tid] = f2tf(w1.x);
        sB[0][5 * 136 + tid] = f2tf(w1.y);
        sB[0][6 * 136 + tid] = f2tf(w1.z);
        sB[0][7 * 136 + tid] = f2tf(w1.w);
    }
    __syncthreads();

    float d[16][4];
#pragma unroll
    for (int nt = 0; nt < 16; ++nt)
#pragma unroll
        for (int i = 0; i < 4; ++i) d[nt][i] = 0.0f;

    int rbase = warp * 16;
    int ar = rbase + (lane >> 2);

    for (int ks = 0; ks < 16; ++ks) {
        int k0 = ks * 8;
        int cur = ks & 1;

        // prefetch next W chunk into registers (overlaps with MMA below)
        float4 w0, w1;
        if (ks < 15) {
            const float4* wr = (const float4*)(W + (size_t)tid * 128 + k0 + 8);
            w0 = wr[0]; w1 = wr[1];
        }

        unsigned a0 = sA[ar * 132 + k0 + (lane & 3)];
        unsigned a1 = sA[(ar + 8) * 132 + k0 + (lane & 3)];
        unsigned a2 = sA[ar * 132 + k0 + (lane & 3) + 4];
        unsigned a3 = sA[(ar + 8) * 132 + k0 + (lane & 3) + 4];

        const unsigned* bb = sB[cur];
        int brow0 = (lane & 3) * 136 + (lane >> 2);
        int brow1 = brow0 + 4 * 136;
#pragma unroll
        for (int nt = 0; nt < 16; ++nt) {
            unsigned b0 = bb[brow0 + nt * 8];
            unsigned b1 = bb[brow1 + nt * 8];
            asm("mma.sync.aligned.m16n8k8.row.col.f32.tf32.tf32.f32 "
                "{%0,%1,%2,%3}, {%4,%5,%6,%7}, {%8,%9}, {%0,%1,%2,%3};"
                : "+f"(d[nt][0]), "+f"(d[nt][1]), "+f"(d[nt][2]), "+f"(d[nt][3])
                : "r"(a0), "r"(a1), "r"(a2), "r"(a3), "r"(b0), "r"(b1));
        }

        if (ks < 15) {
            unsigned* nb = sB[cur ^ 1];
            nb[0 * 136 + tid] = f2tf(w0.x);
            nb[1 * 136 + tid] = f2tf(w0.y);
            nb[2 * 136 + tid] = f2tf(w0.z);
            nb[3 * 136 + tid] = f2tf(w0.w);
            nb[4 * 136 + tid] = f2tf(w1.x);
            nb[5 * 136 + tid] = f2tf(w1.y);
            nb[6 * 136 + tid] = f2tf(w1.z);
            nb[7 * 136 + tid] = f2tf(w1.w);
        }
        __syncthreads();
    }

    int r0 = row0 + rbase + (lane >> 2);
#pragma unroll
    for (int nt = 0; nt < 16; ++nt) {
        int col = nt * 8 + 2 * (lane & 3);
        if (r0 < n)
            *(float2*)&C[(size_t)r0 * 128 + col] = make_float2(d[nt][0], d[nt][1]);
        if (r0 + 8 < n)
            *(float2*)&C[(size_t)(r0 + 8) * 128 + col] = make_float2(d[nt][2], d[nt][3]);
    }
}

// ---------------- gather + bias + relu + fused BN stats ----------------
__global__ void __launch_bounds__(512)
k_gather(const float* __restrict__ bias) {
    __shared__ float ssum[DIM], ssq[DIM];
    int tid = threadIdx.x;
    if (tid < DIM) { ssum[tid] = 0.0f; ssq[tid] = 0.0f; }
    __syncthreads();

    int node = blockIdx.x * 16 + (tid >> 5);
    int lane = tid & 31;

    if (node < NN) {
        float dv = g_dinv[node];
        float sw = dv * dv;
        float4 v = g_B4[(size_t)node * 32 + lane];
        float4 acc = make_float4(v.x * sw, v.y * sw, v.z * sw, v.w * sw);

        int s = g_start[node], e = g_start[node + 1];
        int j = s;
        for (; j + 1 < e; j += 2) {
            int2 c0 = g_csr[j];
            int2 c1 = g_csr[j + 1];
            float4 u0 = g_B4[(size_t)c0.x * 32 + lane];
            float4 u1 = g_B4[(size_t)c1.x * 32 + lane];
            float w0 = __int_as_float(c0.y);
            float w1 = __int_as_float(c1.y);
            acc.x = fmaf(w0, u0.x, acc.x); acc.y = fmaf(w0, u0.y, acc.y);
            acc.z = fmaf(w0, u0.z, acc.z); acc.w = fmaf(w0, u0.w, acc.w);
            acc.x = fmaf(w1, u1.x, acc.x); acc.y = fmaf(w1, u1.y, acc.y);
            acc.z = fmaf(w1, u1.z, acc.z); acc.w = fmaf(w1, u1.w, acc.w);
        }
        if (j < e) {
            int2 c0 = g_csr[j];
            float4 u0 = g_B4[(size_t)c0.x * 32 + lane];
            float w0 = __int_as_float(c0.y);
            acc.x = fmaf(w0, u0.x, acc.x); acc.y = fmaf(w0, u0.y, acc.y);
            acc.z = fmaf(w0, u0.z, acc.z); acc.w = fmaf(w0, u0.w, acc.w);
        }

        float4 bc = ((const float4*)bias)[lane];
        acc.x = fmaxf(acc.x + bc.x, 0.0f);
        acc.y = fmaxf(acc.y + bc.y, 0.0f);
        acc.z = fmaxf(acc.z + bc.z, 0.0f);
        acc.w = fmaxf(acc.w + bc.w, 0.0f);
        g_A4[(size_t)node * 32 + lane] = acc;

        int cb = lane * 4;
        atomicAdd(&ssum[cb + 0], acc.x); atomicAdd(&ssq[cb + 0], acc.x * acc.x);
        atomicAdd(&ssum[cb + 1], acc.y); atomicAdd(&ssq[cb + 1], acc.y * acc.y);
        atomicAdd(&ssum[cb + 2], acc.z); atomicAdd(&ssq[cb + 2], acc.z * acc.z);
        atomicAdd(&ssum[cb + 3], acc.w); atomicAdd(&ssq[cb + 3], acc.w * acc.w);
    }
    __syncthreads();
    if (tid < DIM) {
        atomicAdd(&g_sum[tid], ssum[tid]);
        atomicAdd(&g_sumsq[tid], ssq[tid]);
    }
}

__global__ void k_bnfinal(const float* __restrict__ gamma, const float* __restrict__ beta) {
    int c = threadIdx.x;
    float mean = g_sum[c] * (1.0f / NN);
    float var  = fmaxf(g_sumsq[c] * (1.0f / NN) - mean * mean, 0.0f);
    float inv  = rsqrtf(var + BN_EPS);
    float sc   = gamma[c] * inv;
    g_scale[c] = sc;
    g_shift[c] = beta[c] - mean * sc;
}

// BN-apply -> xs slice only (g_A stays pre-BN; next GEMM applies affine at load)
__global__ void k_apply(float* __restrict__ xs_dst, int l) {
    long long t = (long long)blockIdx.x * blockDim.x + threadIdx.x;
    if (t < DIM) { g_sum[t] = 0.0f; g_sumsq[t] = 0.0f; }
    if (t >= (long long)NN * DIM) return;
    int c = (int)(t & 127);
    long long i = t >> 7;
    const float* Af = (const float*)g_A4;
    float y = fmaf(Af[t], g_scale[c], g_shift[c]);
    xs_dst[i * (LL * DIM) + (size_t)l * DIM + c] = y;
}

__global__ void k_pool(const float* __restrict__ xs, float* __restrict__ out) {
    int g = blockIdx.x;
    int c = threadIdx.x;
    int s = g_off[g], e = g_off[g + 1];
    float acc = 0.0f;
    for (int i = s; i < e; ++i) acc += xs[(size_t)i * (LL * DIM) + c];
    out[(size_t)g * (LL * DIM) + c] = acc;
}

__global__ void k_copy_xs(float* __restrict__ dst, long long count) {
    long long t = (long long)blockIdx.x * blockDim.x + threadIdx.x;
    if (t < count) dst[t] = g_xs[t];
}

// ---------------- launch (kernel launches ONLY) ----------------
extern "C" void kernel_launch(void* const* d_in, const int* in_sizes, int n_in,
                              void* d_out, int out_size) {
    const float* x     = (const float*)d_in[0];
    const int*   ei    = (const int*)d_in[1];
    const float* ew    = (const float*)d_in[2];
    const int*   batch = (const int*)d_in[3];
    const float* fc_w  = (const float*)d_in[4];
    const float* W     = (const float*)d_in[5];
    const float* b     = (const float*)d_in[6];
    const float* gamma = (const float*)d_in[7];
    const float* beta  = (const float*)d_in[8];

    float* out = (float*)d_out;

    const long long pool_elems = (long long)GG * LL * DIM;
    const long long xs_elems   = (long long)NN * LL * DIM;
    long long rem = (long long)out_size - pool_elems;
    bool direct = (rem >= xs_elems);
    float* xs_out_tail = out + pool_elems;

    const int T = 256;
    int nb_N  = (NN + T - 1) / T;
    int nb_E  = (EE + T - 1) / T;
    int nb_AP = (int)(((long long)NN * DIM + T - 1) / T);
    int nb_G  = (NN + 63) / 64;
    int nb_GA = (NN + 15) / 16;

    // prep
    k_init<<<nb_N, T>>>();
    k_deg<<<nb_E, T>>>(ei, ew);
    k_dinv<<<nb_N, T>>>();
    k_scan_blk<<<NBLK, SCAN_B>>>();
    k_scan_mid<<<1, 32>>>();
    k_scan_add<<<nb_N, T>>>();
    k_fill<<<nb_E, T>>>(ei, ew);
    k_count<<<nb_N, T>>>(batch);
    k_scan_graphs<<<1, 32>>>();

    // h0 = x @ fc_w^T -> g_A (no affine)
    k_gemm_tc<<<nb_G, 128>>>(x, fc_w, 0, 0, NN);

    for (int l = 0; l < LL; ++l) {
        k_gemm_tc<<<nb_G, 128>>>(nullptr, W + (size_t)l * DIM * DIM, 1, l > 0 ? 1 : 0, NN);
        k_gather<<<nb_GA, 512>>>(b + (size_t)l * DIM);
        k_bnfinal<<<1, 128>>>(gamma + (size_t)l * DIM, beta + (size_t)l * DIM);
        if (direct)
            k_apply<<<nb_AP, T>>>(xs_out_tail, l);
        else
            k_apply<<<nb_AP, T>>>(g_xs, l);
    }

    if ((long long)out_size >= pool_elems) {
        if (direct)
            k_pool<<<GG, LL * DIM>>>(xs_out_tail, out);
        else
            k_pool<<<GG, LL * DIM>>>(g_xs, out);
    }

    if (!direct && rem > 0) {
        long long cnt = rem < xs_elems ? rem : xs_elems;
        int nb_CP = (int)((cnt + T - 1) / T);
        k_copy_xs<<<nb_CP, T>>>(out + pool_elems, cnt);
    }
}

// round 13
// speedup vs baseline: 1.7705x; 1.1161x over previous
#include <cuda_runtime.h>

#define NN 100000
#define EE 1600000
#define GG 512
#define LL 3
#define DIM 128
#define BN_EPS 1e-5f
#define SCAN_B 1024
#define NBLK ((NN + SCAN_B - 1) / SCAN_B)   // 98
#define APCH 64                             // nodes per apply_pool block

// ---------------- scratch (static device globals; no allocation) ----------------
__device__ float4 g_A4[(size_t)NN * 32];       // activation (pre-BN after gather)
__device__ float4 g_B4[(size_t)NN * 32];       // per-layer linear output (hl)
__device__ float  g_xs[(size_t)NN * LL * DIM]; // fallback staging
__device__ float  g_deg[NN];
__device__ float  g_dinv[NN];
__device__ int    g_indeg[NN];
__device__ int    g_start[NN + 1];
__device__ int    g_cursor[NN];
__device__ int2   g_csr[EE];                   // (src, weight bits)
__device__ int    g_part[NBLK];
__device__ float  g_sum[DIM];
__device__ float  g_sumsq[DIM];
__device__ float  g_scale[DIM];
__device__ float  g_shift[DIM];

// ---------------- prep ----------------
__global__ void k_init() {
    int i = blockIdx.x * blockDim.x + threadIdx.x;
    if (i < NN) { g_deg[i] = 1.0f; g_indeg[i] = 0; }
    if (i < DIM) { g_sum[i] = 0.0f; g_sumsq[i] = 0.0f; }
}

__global__ void k_deg(const int* __restrict__ ei, const float* __restrict__ ew) {
    int e = blockIdx.x * blockDim.x + threadIdx.x;
    if (e >= EE) return;
    int c = ei[EE + e];
    atomicAdd(&g_deg[c], ew[e]);
    atomicAdd(&g_indeg[c], 1);
}

__global__ void k_dinv() {
    int i = blockIdx.x * blockDim.x + threadIdx.x;
    if (i < NN) g_dinv[i] = rsqrtf(g_deg[i]);
}

__global__ void k_scan_blk() {
    __shared__ int sh[SCAN_B];
    int t = threadIdx.x;
    int i = blockIdx.x * SCAN_B + t;
    int v = (i < NN) ? g_indeg[i] : 0;
    sh[t] = v;
    __syncthreads();
    for (int off = 1; off < SCAN_B; off <<= 1) {
        int u = (t >= off) ? sh[t - off] : 0;
        __syncthreads();
        sh[t] += u;
        __syncthreads();
    }
    if (i < NN) g_start[i] = sh[t] - v;
    if (t == SCAN_B - 1) g_part[blockIdx.x] = sh[t];
}

__global__ void k_scan_mid() {
    if (threadIdx.x == 0) {
        int acc = 0;
        for (int b = 0; b < NBLK; ++b) { int u = g_part[b]; g_part[b] = acc; acc += u; }
    }
}

__global__ void k_scan_add() {
    int i = blockIdx.x * blockDim.x + threadIdx.x;
    if (i < NN) {
        int s = g_start[i] + g_part[i >> 10];
        g_start[i]  = s;
        g_cursor[i] = s;
    }
    if (i == 0) g_start[NN] = EE;
}

__global__ void k_fill(const int* __restrict__ ei, const float* __restrict__ ew) {
    int e = blockIdx.x * blockDim.x + threadIdx.x;
    if (e >= EE) return;
    int r = ei[e];
    int c = ei[EE + e];
    int slot = atomicAdd(&g_cursor[c], 1);
    float w = g_dinv[r] * ew[e] * g_dinv[c];
    g_csr[slot] = make_int2(r, __float_as_int(w));
}

// ---------------- zero the pooled-output region (accumulated via atomics) ----------------
__global__ void k_zero_out(float* __restrict__ out) {
    int i = blockIdx.x * blockDim.x + threadIdx.x;
    if (i < GG * LL * DIM) out[i] = 0.0f;
}

// ---------------- tf32 tensor-core GEMM: C[i][j] = sum_k A'[i][k] * W[j][k] ----------------
__device__ __forceinline__ unsigned f2tf(float f) {
    unsigned u;
    asm("cvt.rna.tf32.f32 %0, %1;" : "=r"(u) : "f"(f));
    return u;
}

__global__ void __launch_bounds__(128)
k_gemm_tc(const float* __restrict__ Ain, const float* __restrict__ W,
          int mode, int affine, int n) {
    __shared__ unsigned sA[64 * 132];      // 33792 B (a-frag conflict-free)
    __shared__ unsigned sB[2][8 * 136];    // 8704 B  (b-frag conflict-free)

    const float* A = mode ? (const float*)g_A4 : Ain;
    float*       C = mode ? (float*)g_B4 : (float*)g_A4;

    int tid  = threadIdx.x;
    int warp = tid >> 5;
    int lane = tid & 31;
    int row0 = blockIdx.x * 64;

    for (int idx = tid; idx < 64 * 32; idx += 128) {
        int r = idx >> 5, c4 = idx & 31;
        int gr = row0 + r;
        float4 v = (gr < n) ? ((const float4*)A)[(size_t)gr * 32 + c4]
                            : make_float4(0.f, 0.f, 0.f, 0.f);
        if (affine) {
            float4 sc = ((const float4*)g_scale)[c4];
            float4 sh = ((const float4*)g_shift)[c4];
            v.x = fmaf(v.x, sc.x, sh.x);
            v.y = fmaf(v.y, sc.y, sh.y);
            v.z = fmaf(v.z, sc.z, sh.z);
            v.w = fmaf(v.w, sc.w, sh.w);
        }
        uint4 p = make_uint4(f2tf(v.x), f2tf(v.y), f2tf(v.z), f2tf(v.w));
        *(uint4*)&sA[(size_t)r * 132 + c4 * 4] = p;
    }

    {
        const float4* wr = (const float4*)(W + (size_t)tid * 128);
        float4 w0 = wr[0], w1 = wr[1];
        sB[0][0 * 136 + tid] = f2tf(w0.x);
        sB[0][1 * 136 + tid] = f2tf(w0.y);
        sB[0][2 * 136 + tid] = f2tf(w0.z);
        sB[0][3 * 136 + tid] = f2tf(w0.w);
        sB[0][4 * 136 + tid] = f2tf(w1.x);
        sB[0][5 * 136 + tid] = f2tf(w1.y);
        sB[0][6 * 136 + tid] = f2tf(w1.z);
        sB[0][7 * 136 + tid] = f2tf(w1.w);
    }
    __syncthreads();

    float d[16][4];
#pragma unroll
    for (int nt = 0; nt < 16; ++nt)
#pragma unroll
        for (int i = 0; i < 4; ++i) d[nt][i] = 0.0f;

    int rbase = warp * 16;
    int ar = rbase + (lane >> 2);

    for (int ks = 0; ks < 16; ++ks) {
        int k0 = ks * 8;
        int cur = ks & 1;

        float4 w0, w1;
        if (ks < 15) {
            const float4* wr = (const float4*)(W + (size_t)tid * 128 + k0 + 8);
            w0 = wr[0]; w1 = wr[1];
        }

        unsigned a0 = sA[ar * 132 + k0 + (lane & 3)];
        unsigned a1 = sA[(ar + 8) * 132 + k0 + (lane & 3)];
        unsigned a2 = sA[ar * 132 + k0 + (lane & 3) + 4];
        unsigned a3 = sA[(ar + 8) * 132 + k0 + (lane & 3) + 4];

        const unsigned* bb = sB[cur];
        int brow0 = (lane & 3) * 136 + (lane >> 2);
        int brow1 = brow0 + 4 * 136;
#pragma unroll
        for (int nt = 0; nt < 16; ++nt) {
            unsigned b0 = bb[brow0 + nt * 8];
            unsigned b1 = bb[brow1 + nt * 8];
            asm("mma.sync.aligned.m16n8k8.row.col.f32.tf32.tf32.f32 "
                "{%0,%1,%2,%3}, {%4,%5,%6,%7}, {%8,%9}, {%0,%1,%2,%3};"
                : "+f"(d[nt][0]), "+f"(d[nt][1]), "+f"(d[nt][2]), "+f"(d[nt][3])
                : "r"(a0), "r"(a1), "r"(a2), "r"(a3), "r"(b0), "r"(b1));
        }

        if (ks < 15) {
            unsigned* nb = sB[cur ^ 1];
            nb[0 * 136 + tid] = f2tf(w0.x);
            nb[1 * 136 + tid] = f2tf(w0.y);
            nb[2 * 136 + tid] = f2tf(w0.z);
            nb[3 * 136 + tid] = f2tf(w0.w);
            nb[4 * 136 + tid] = f2tf(w1.x);
            nb[5 * 136 + tid] = f2tf(w1.y);
            nb[6 * 136 + tid] = f2tf(w1.z);
            nb[7 * 136 + tid] = f2tf(w1.w);
        }
        __syncthreads();
    }

    int r0 = row0 + rbase + (lane >> 2);
#pragma unroll
    for (int nt = 0; nt < 16; ++nt) {
        int col = nt * 8 + 2 * (lane & 3);
        if (r0 < n)
            *(float2*)&C[(size_t)r0 * 128 + col] = make_float2(d[nt][0], d[nt][1]);
        if (r0 + 8 < n)
            *(float2*)&C[(size_t)(r0 + 8) * 128 + col] = make_float2(d[nt][2], d[nt][3]);
    }
}

// ---------------- gather + bias + relu + fused BN stats ----------------
__global__ void __launch_bounds__(512)
k_gather(const float* __restrict__ bias) {
    __shared__ float ssum[DIM], ssq[DIM];
    int tid = threadIdx.x;
    if (tid < DIM) { ssum[tid] = 0.0f; ssq[tid] = 0.0f; }
    __syncthreads();

    int node = blockIdx.x * 16 + (tid >> 5);
    int lane = tid & 31;

    if (node < NN) {
        float dv = g_dinv[node];
        float sw = dv * dv;
        float4 v = g_B4[(size_t)node * 32 + lane];
        float4 acc = make_float4(v.x * sw, v.y * sw, v.z * sw, v.w * sw);

        int s = g_start[node], e = g_start[node + 1];
        int j = s;
        for (; j + 3 < e; j += 4) {             // 4-deep for MLP
            int2 c0 = g_csr[j];
            int2 c1 = g_csr[j + 1];
            int2 c2 = g_csr[j + 2];
            int2 c3 = g_csr[j + 3];
            float4 u0 = g_B4[(size_t)c0.x * 32 + lane];
            float4 u1 = g_B4[(size_t)c1.x * 32 + lane];
            float4 u2 = g_B4[(size_t)c2.x * 32 + lane];
            float4 u3 = g_B4[(size_t)c3.x * 32 + lane];
            float w0 = __int_as_float(c0.y);
            float w1 = __int_as_float(c1.y);
            float w2 = __int_as_float(c2.y);
            float w3 = __int_as_float(c3.y);
            acc.x = fmaf(w0, u0.x, acc.x); acc.y = fmaf(w0, u0.y, acc.y);
            acc.z = fmaf(w0, u0.z, acc.z); acc.w = fmaf(w0, u0.w, acc.w);
            acc.x = fmaf(w1, u1.x, acc.x); acc.y = fmaf(w1, u1.y, acc.y);
            acc.z = fmaf(w1, u1.z, acc.z); acc.w = fmaf(w1, u1.w, acc.w);
            acc.x = fmaf(w2, u2.x, acc.x); acc.y = fmaf(w2, u2.y, acc.y);
            acc.z = fmaf(w2, u2.z, acc.z); acc.w = fmaf(w2, u2.w, acc.w);
            acc.x = fmaf(w3, u3.x, acc.x); acc.y = fmaf(w3, u3.y, acc.y);
            acc.z = fmaf(w3, u3.z, acc.z); acc.w = fmaf(w3, u3.w, acc.w);
        }
        for (; j < e; ++j) {
            int2 c0 = g_csr[j];
            float4 u0 = g_B4[(size_t)c0.x * 32 + lane];
            float w0 = __int_as_float(c0.y);
            acc.x = fmaf(w0, u0.x, acc.x); acc.y = fmaf(w0, u0.y, acc.y);
            acc.z = fmaf(w0, u0.z, acc.z); acc.w = fmaf(w0, u0.w, acc.w);
        }

        float4 bc = ((const float4*)bias)[lane];
        acc.x = fmaxf(acc.x + bc.x, 0.0f);
        acc.y = fmaxf(acc.y + bc.y, 0.0f);
        acc.z = fmaxf(acc.z + bc.z, 0.0f);
        acc.w = fmaxf(acc.w + bc.w, 0.0f);
        g_A4[(size_t)node * 32 + lane] = acc;

        int cb = lane * 4;
        atomicAdd(&ssum[cb + 0], acc.x); atomicAdd(&ssq[cb + 0], acc.x * acc.x);
        atomicAdd(&ssum[cb + 1], acc.y); atomicAdd(&ssq[cb + 1], acc.y * acc.y);
        atomicAdd(&ssum[cb + 2], acc.z); atomicAdd(&ssq[cb + 2], acc.z * acc.z);
        atomicAdd(&ssum[cb + 3], acc.w); atomicAdd(&ssq[cb + 3], acc.w * acc.w);
    }
    __syncthreads();
    if (tid < DIM) {
        atomicAdd(&g_sum[tid], ssum[tid]);
        atomicAdd(&g_sumsq[tid], ssq[tid]);
    }
}

__global__ void k_bnfinal(const float* __restrict__ gamma, const float* __restrict__ beta) {
    int c = threadIdx.x;
    float mean = g_sum[c] * (1.0f / NN);
    float var  = fmaxf(g_sumsq[c] * (1.0f / NN) - mean * mean, 0.0f);
    float inv  = rsqrtf(var + BN_EPS);
    float sc   = gamma[c] * inv;
    g_scale[c] = sc;
    g_shift[c] = beta[c] - mean * sc;
}

// ---------------- BN-apply + xs write + fused segment pooling ----------------
// batch is sorted: block owns APCH contiguous nodes, keeps per-column running
// sum, atomicAdd at graph boundaries. Also zeroes stats for next layer.
__global__ void __launch_bounds__(128)
k_apply_pool(const int* __restrict__ batch, float* __restrict__ xs_dst,
             float* __restrict__ out, int l) {
    int c  = threadIdx.x;                      // column 0..127
    int n0 = blockIdx.x * APCH;
    int n1 = min(n0 + APCH, NN);
    if (blockIdx.x == 0) { g_sum[c] = 0.0f; g_sumsq[c] = 0.0f; }

    float sc = g_scale[c], sh = g_shift[c];
    const float* Af = (const float*)g_A4;
    float acc = 0.0f;
    int curg = batch[n0];
    for (int i = n0; i < n1; ++i) {
        int gI = batch[i];
        if (gI != curg) {
            atomicAdd(&out[(size_t)curg * (LL * DIM) + l * DIM + c], acc);
            acc = 0.0f;
            curg = gI;
        }
        float y = fmaf(Af[(size_t)i * 128 + c], sc, sh);
        xs_dst[(size_t)i * (LL * DIM) + (size_t)l * DIM + c] = y;
        acc += y;
    }
    atomicAdd(&out[(size_t)curg * (LL * DIM) + l * DIM + c], acc);
}

__global__ void k_copy_xs(float* __restrict__ dst, long long count) {
    long long t = (long long)blockIdx.x * blockDim.x + threadIdx.x;
    if (t < count) dst[t] = g_xs[t];
}

// ---------------- launch (kernel launches ONLY) ----------------
extern "C" void kernel_launch(void* const* d_in, const int* in_sizes, int n_in,
                              void* d_out, int out_size) {
    const float* x     = (const float*)d_in[0];
    const int*   ei    = (const int*)d_in[1];
    const float* ew    = (const float*)d_in[2];
    const int*   batch = (const int*)d_in[3];
    const float* fc_w  = (const float*)d_in[4];
    const float* W     = (const float*)d_in[5];
    const float* b     = (const float*)d_in[6];
    const float* gamma = (const float*)d_in[7];
    const float* beta  = (const float*)d_in[8];

    float* out = (float*)d_out;

    const long long pool_elems = (long long)GG * LL * DIM;
    const long long xs_elems   = (long long)NN * LL * DIM;
    long long rem = (long long)out_size - pool_elems;
    bool direct = (rem >= xs_elems);
    float* xs_out_tail = out + pool_elems;

    const int T = 256;
    int nb_N  = (NN + T - 1) / T;
    int nb_E  = (EE + T - 1) / T;
    int nb_G  = (NN + 63) / 64;
    int nb_GA = (NN + 15) / 16;
    int nb_AP = (NN + APCH - 1) / APCH;
    int nb_ZO = (GG * LL * DIM + T - 1) / T;

    // prep
    k_init<<<nb_N, T>>>();
    k_deg<<<nb_E, T>>>(ei, ew);
    k_dinv<<<nb_N, T>>>();
    k_scan_blk<<<NBLK, SCAN_B>>>();
    k_scan_mid<<<1, 32>>>();
    k_scan_add<<<nb_N, T>>>();
    k_fill<<<nb_E, T>>>(ei, ew);
    if ((long long)out_size >= pool_elems)
        k_zero_out<<<nb_ZO, T>>>(out);

    // h0 = x @ fc_w^T -> g_A (no affine)
    k_gemm_tc<<<nb_G, 128>>>(x, fc_w, 0, 0, NN);

    for (int l = 0; l < LL; ++l) {
        k_gemm_tc<<<nb_G, 128>>>(nullptr, W + (size_t)l * DIM * DIM, 1, l > 0 ? 1 : 0, NN);
        k_gather<<<nb_GA, 512>>>(b + (size_t)l * DIM);
        k_bnfinal<<<1, 128>>>(gamma + (size_t)l * DIM, beta + (size_t)l * DIM);
        if ((long long)out_size >= pool_elems) {
            if (direct)
                k_apply_pool<<<nb_AP, 128>>>(batch, xs_out_tail, out, l);
            else
                k_apply_pool<<<nb_AP, 128>>>(batch, g_xs, out, l);
        }
    }

    if (!direct && rem > 0) {
        long long cnt = rem < xs_elems ? rem : xs_elems;
        int nb_CP = (int)((cnt + T - 1) / T);
        k_copy_xs<<<nb_CP, T>>>(out + pool_elems, cnt);
    }
}

// round 15
// speedup vs baseline: 1.8347x; 1.0363x over previous
#include <cuda_runtime.h>

#define NN 100000
#define EE 1600000
#define GG 512
#define LL 3
#define DIM 128
#define BN_EPS 1e-5f
#define SCAN_B 1024
#define NBLK ((NN + SCAN_B - 1) / SCAN_B)   // 98
#define APCH 64                             // nodes per apply_pool block
#define SB_ROW 388                          // sB k-row stride (mod 32 = 4)
#define SB_NG  48                           // sB n-group stride (mod 32 = 16)

// ---------------- scratch (static device globals; no allocation) ----------------
__device__ float4 g_A4[(size_t)NN * 32];       // activation (pre-BN after gather)
__device__ float4 g_B4[(size_t)NN * 32];       // per-layer linear output (hl)
__device__ float  g_xs[(size_t)NN * LL * DIM]; // fallback staging
__device__ float  g_deg[NN];
__device__ float  g_dinv[NN];
__device__ int    g_indeg[NN];
__device__ int    g_start[NN + 1];
__device__ int    g_cursor[NN];
__device__ int2   g_csr[EE];                   // (src, weight bits)
__device__ int    g_part[NBLK];
__device__ float  g_sumL[LL * DIM];            // per-layer BN stats
__device__ float  g_sumsqL[LL * DIM];

// ---------------- prep ----------------
__global__ void k_init(float* __restrict__ out, long long out_count) {
    int i = blockIdx.x * blockDim.x + threadIdx.x;
    if (i < NN) { g_deg[i] = 1.0f; g_indeg[i] = 0; }
    if (i < LL * DIM) { g_sumL[i] = 0.0f; g_sumsqL[i] = 0.0f; }
    for (long long j = i; j < out_count; j += (long long)gridDim.x * blockDim.x)
        out[j] = 0.0f;
}

__global__ void k_deg(const int* __restrict__ ei, const float* __restrict__ ew) {
    int e = blockIdx.x * blockDim.x + threadIdx.x;
    if (e >= EE) return;
    int c = ei[EE + e];
    atomicAdd(&g_deg[c], ew[e]);
    atomicAdd(&g_indeg[c], 1);
}

__global__ void k_scan_blk() {
    __shared__ int sh[SCAN_B];
    int t = threadIdx.x;
    int i = blockIdx.x * SCAN_B + t;
    int v = (i < NN) ? g_indeg[i] : 0;
    sh[t] = v;
    __syncthreads();
    for (int off = 1; off < SCAN_B; off <<= 1) {
        int u = (t >= off) ? sh[t - off] : 0;
        __syncthreads();
        sh[t] += u;
        __syncthreads();
    }
    if (i < NN) g_start[i] = sh[t] - v;
    if (t == SCAN_B - 1) g_part[blockIdx.x] = sh[t];
}

__global__ void k_scan_mid() {
    if (threadIdx.x == 0) {
        int acc = 0;
        for (int b = 0; b < NBLK; ++b) { int u = g_part[b]; g_part[b] = acc; acc += u; }
    }
}

// scan finalize + dinv + cursor init (folded)
__global__ void k_scan_add() {
    int i = blockIdx.x * blockDim.x + threadIdx.x;
    if (i < NN) {
        int s = g_start[i] + g_part[i >> 10];
        g_start[i]  = s;
        g_cursor[i] = s;
        g_dinv[i]   = rsqrtf(g_deg[i]);
    }
    if (i == 0) g_start[NN] = EE;
}

__global__ void k_fill(const int* __restrict__ ei, const float* __restrict__ ew) {
    int e = blockIdx.x * blockDim.x + threadIdx.x;
    if (e >= EE) return;
    int r = ei[e];
    int c = ei[EE + e];
    int slot = atomicAdd(&g_cursor[c], 1);
    float w = g_dinv[r] * ew[e] * g_dinv[c];
    g_csr[slot] = make_int2(r, __float_as_int(w));
}

// ---------------- tf32 tensor-core GEMM: C[i][j] = sum_k A'[i][k] * W[j][k] ----------------
// A' = BN-affine of A (stats_l >= 0) or A. 128 threads, 64 rows/block.
// sB layout: sB[(k&3)*SB_ROW + (n&7)*SB_NG + (n>>3)*2 + (k>>2)]
//   -> one LDS.128 per warp yields b0/b1 for two consecutive nt tiles, conflict-free.
__device__ __forceinline__ unsigned f2tf(float f) {
    unsigned u;
    asm("cvt.rna.tf32.f32 %0, %1;" : "=r"(u) : "f"(f));
    return u;
}

__global__ void __launch_bounds__(128)
k_gemm_tc(const float* __restrict__ Ain, const float* __restrict__ W,
          const float* __restrict__ gamma, const float* __restrict__ beta,
          int mode, int stats_l, int n) {
    __shared__ unsigned sA[64 * 132];        // 33792 B (a-frag conflict-free)
    __shared__ unsigned sB[2][4 * SB_ROW];   // 12416 B (b-frag conflict-free, vectorized)
    __shared__ float sSc[DIM], sSh[DIM];

    const float* A = mode ? (const float*)g_A4 : Ain;
    float*       C = mode ? (float*)g_B4 : (float*)g_A4;

    int tid  = threadIdx.x;
    int warp = tid >> 5;
    int lane = tid & 31;
    int row0 = blockIdx.x * 64;

    if (stats_l >= 0) {
        if (tid < DIM) {
            float mean = g_sumL[stats_l * DIM + tid] * (1.0f / NN);
            float var  = fmaxf(g_sumsqL[stats_l * DIM + tid] * (1.0f / NN) - mean * mean, 0.0f);
            float sc   = gamma[tid] * rsqrtf(var + BN_EPS);
            sSc[tid] = sc;
            sSh[tid] = beta[tid] - mean * sc;
        }
        __syncthreads();
    }

    // load A tile (affine applied, converted to tf32 bits)
    for (int idx = tid; idx < 64 * 32; idx += 128) {
        int r = idx >> 5, c4 = idx & 31;
        int gr = row0 + r;
        float4 v = (gr < n) ? ((const float4*)A)[(size_t)gr * 32 + c4]
                            : make_float4(0.f, 0.f, 0.f, 0.f);
        if (stats_l >= 0) {
            float4 sc = *(const float4*)&sSc[c4 * 4];
            float4 sh = *(const float4*)&sSh[c4 * 4];
            v.x = fmaf(v.x, sc.x, sh.x);
            v.y = fmaf(v.y, sc.y, sh.y);
            v.z = fmaf(v.z, sc.z, sh.z);
            v.w = fmaf(v.w, sc.w, sh.w);
        }
        uint4 p = make_uint4(f2tf(v.x), f2tf(v.y), f2tf(v.z), f2tf(v.w));
        *(uint4*)&sA[(size_t)r * 132 + c4 * 4] = p;
    }

    // preload W chunk 0 (thread tid owns output column n = tid, k = 0..7)
    {
        const float4* wr = (const float4*)(W + (size_t)tid * 128);
        float4 w0 = wr[0], w1 = wr[1];            // k 0..3, 4..7
        unsigned base = (tid & 7) * SB_NG + (tid >> 3) * 2;
        unsigned* nb = sB[0];
        uint2 p;
        p.x = f2tf(w0.x); p.y = f2tf(w1.x); *(uint2*)&nb[base + 0 * SB_ROW] = p;
        p.x = f2tf(w0.y); p.y = f2tf(w1.y); *(uint2*)&nb[base + 1 * SB_ROW] = p;
        p.x = f2tf(w0.z); p.y = f2tf(w1.z); *(uint2*)&nb[base + 2 * SB_ROW] = p;
        p.x = f2tf(w0.w); p.y = f2tf(w1.w); *(uint2*)&nb[base + 3 * SB_ROW] = p;
    }
    __syncthreads();

    float d[16][4];
#pragma unroll
    for (int nt = 0; nt < 16; ++nt)
#pragma unroll
        for (int i = 0; i < 4; ++i) d[nt][i] = 0.0f;

    int rbase = warp * 16;
    int ar = rbase + (lane >> 2);
    int bbase = (lane & 3) * SB_ROW + (lane >> 2) * SB_NG;

    for (int ks = 0; ks < 16; ++ks) {
        int k0 = ks * 8;
        int cur = ks & 1;

        float4 w0, w1;
        if (ks < 15) {
            const float4* wr = (const float4*)(W + (size_t)tid * 128 + k0 + 8);
            w0 = wr[0]; w1 = wr[1];
        }

        unsigned a0 = sA[ar * 132 + k0 + (lane & 3)];
        unsigned a1 = sA[(ar + 8) * 132 + k0 + (lane & 3)];
        unsigned a2 = sA[ar * 132 + k0 + (lane & 3) + 4];
        unsigned a3 = sA[(ar + 8) * 132 + k0 + (lane & 3) + 4];

        const unsigned* bb = sB[cur];
#pragma unroll
        for (int ntp = 0; ntp < 8; ++ntp) {
            uint4 bv = *(const uint4*)&bb[bbase + ntp * 4];
            asm("mma.sync.aligned.m16n8k8.row.col.f32.tf32.tf32.f32 "
                "{%0,%1,%2,%3}, {%4,%5,%6,%7}, {%8,%9}, {%0,%1,%2,%3};"
                : "+f"(d[2 * ntp][0]), "+f"(d[2 * ntp][1]), "+f"(d[2 * ntp][2]), "+f"(d[2 * ntp][3])
                : "r"(a0), "r"(a1), "r"(a2), "r"(a3), "r"(bv.x), "r"(bv.y));
            asm("mma.sync.aligned.m16n8k8.row.col.f32.tf32.tf32.f32 "
                "{%0,%1,%2,%3}, {%4,%5,%6,%7}, {%8,%9}, {%0,%1,%2,%3};"
                : "+f"(d[2 * ntp + 1][0]), "+f"(d[2 * ntp + 1][1]), "+f"(d[2 * ntp + 1][2]), "+f"(d[2 * ntp + 1][3])
                : "r"(a0), "r"(a1), "r"(a2), "r"(a3), "r"(bv.z), "r"(bv.w));
        }

        if (ks < 15) {
            unsigned base = (tid & 7) * SB_NG + (tid >> 3) * 2;
            unsigned* nb = sB[cur ^ 1];
            uint2 p;
            p.x = f2tf(w0.x); p.y = f2tf(w1.x); *(uint2*)&nb[base + 0 * SB_ROW] = p;
            p.x = f2tf(w0.y); p.y = f2tf(w1.y); *(uint2*)&nb[base + 1 * SB_ROW] = p;
            p.x = f2tf(w0.z); p.y = f2tf(w1.z); *(uint2*)&nb[base + 2 * SB_ROW] = p;
            p.x = f2tf(w0.w); p.y = f2tf(w1.w); *(uint2*)&nb[base + 3 * SB_ROW] = p;
        }
        __syncthreads();
    }

    int r0 = row0 + rbase + (lane >> 2);
#pragma unroll
    for (int nt = 0; nt < 16; ++nt) {
        int col = nt * 8 + 2 * (lane & 3);
        if (r0 < n)
            *(float2*)&C[(size_t)r0 * 128 + col] = make_float2(d[nt][0], d[nt][1]);
        if (r0 + 8 < n)
            *(float2*)&C[(size_t)(r0 + 8) * 128 + col] = make_float2(d[nt][2], d[nt][3]);
    }
}

// ---------------- gather + bias + relu + fused BN stats (per-layer buffer) ----------------
__global__ void __launch_bounds__(512)
k_gather(const float* __restrict__ bias, int l) {
    __shared__ float ssum[DIM], ssq[DIM];
    int tid = threadIdx.x;
    if (tid < DIM) { ssum[tid] = 0.0f; ssq[tid] = 0.0f; }
    __syncthreads();

    int node = blockIdx.x * 16 + (tid >> 5);
    int lane = tid & 31;

    if (node < NN) {
        float dv = g_dinv[node];
        float sw = dv * dv;
        float4 v = g_B4[(size_t)node * 32 + lane];
        float4 acc = make_float4(v.x * sw, v.y * sw, v.z * sw, v.w * sw);

        int s = g_start[node], e = g_start[node + 1];
        int j = s;
        for (; j + 3 < e; j += 4) {
            int2 c0 = g_csr[j];
            int2 c1 = g_csr[j + 1];
            int2 c2 = g_csr[j + 2];
            int2 c3 = g_csr[j + 3];
            float4 u0 = g_B4[(size_t)c0.x * 32 + lane];
            float4 u1 = g_B4[(size_t)c1.x * 32 + lane];
            float4 u2 = g_B4[(size_t)c2.x * 32 + lane];
            float4 u3 = g_B4[(size_t)c3.x * 32 + lane];
            float w0 = __int_as_float(c0.y);
            float w1 = __int_as_float(c1.y);
            float w2 = __int_as_float(c2.y);
            float w3 = __int_as_float(c3.y);
            acc.x = fmaf(w0, u0.x, acc.x); acc.y = fmaf(w0, u0.y, acc.y);
            acc.z = fmaf(w0, u0.z, acc.z); acc.w = fmaf(w0, u0.w, acc.w);
            acc.x = fmaf(w1, u1.x, acc.x); acc.y = fmaf(w1, u1.y, acc.y);
            acc.z = fmaf(w1, u1.z, acc.z); acc.w = fmaf(w1, u1.w, acc.w);
            acc.x = fmaf(w2, u2.x, acc.x); acc.y = fmaf(w2, u2.y, acc.y);
            acc.z = fmaf(w2, u2.z, acc.z); acc.w = fmaf(w2, u2.w, acc.w);
            acc.x = fmaf(w3, u3.x, acc.x); acc.y = fmaf(w3, u3.y, acc.y);
            acc.z = fmaf(w3, u3.z, acc.z); acc.w = fmaf(w3, u3.w, acc.w);
        }
        for (; j < e; ++j) {
            int2 c0 = g_csr[j];
            float4 u0 = g_B4[(size_t)c0.x * 32 + lane];
            float w0 = __int_as_float(c0.y);
            acc.x = fmaf(w0, u0.x, acc.x); acc.y = fmaf(w0, u0.y, acc.y);
            acc.z = fmaf(w0, u0.z, acc.z); acc.w = fmaf(w0, u0.w, acc.w);
        }

        float4 bc = ((const float4*)bias)[lane];
        acc.x = fmaxf(acc.x + bc.x, 0.0f);
        acc.y = fmaxf(acc.y + bc.y, 0.0f);
        acc.z = fmaxf(acc.z + bc.z, 0.0f);
        acc.w = fmaxf(acc.w + bc.w, 0.0f);
        g_A4[(size_t)node * 32 + lane] = acc;

        int cb = lane * 4;
        atomicAdd(&ssum[cb + 0], acc.x); atomicAdd(&ssq[cb + 0], acc.x * acc.x);
        atomicAdd(&ssum[cb + 1], acc.y); atomicAdd(&ssq[cb + 1], acc.y * acc.y);
        atomicAdd(&ssum[cb + 2], acc.z); atomicAdd(&ssq[cb + 2], acc.z * acc.z);
        atomicAdd(&ssum[cb + 3], acc.w); atomicAdd(&ssq[cb + 3], acc.w * acc.w);
    }
    __syncthreads();
    if (tid < DIM) {
        atomicAdd(&g_sumL[l * DIM + tid], ssum[tid]);
        atomicAdd(&g_sumsqL[l * DIM + tid], ssq[tid]);
    }
}

// ---------------- BN-apply + xs write + fused segment pooling ----------------
__global__ void __launch_bounds__(128)
k_apply_pool(const int* __restrict__ batch, float* __restrict__ xs_dst,
             float* __restrict__ out,
             const float* __restrict__ gamma, const float* __restrict__ beta, int l) {
    int c  = threadIdx.x;                      // column 0..127
    int n0 = blockIdx.x * APCH;
    int n1 = min(n0 + APCH, NN);

    float mean = g_sumL[l * DIM + c] * (1.0f / NN);
    float var  = fmaxf(g_sumsqL[l * DIM + c] * (1.0f / NN) - mean * mean, 0.0f);
    float sc   = gamma[c] * rsqrtf(var + BN_EPS);
    float sh   = beta[c] - mean * sc;

    const float* Af = (const float*)g_A4;
    float acc = 0.0f;
    int curg = batch[n0];
    for (int i = n0; i < n1; ++i) {
        int gI = batch[i];
        if (gI != curg) {
            atomicAdd(&out[(size_t)curg * (LL * DIM) + l * DIM + c], acc);
            acc = 0.0f;
            curg = gI;
        }
        float y = fmaf(Af[(size_t)i * 128 + c], sc, sh);
        xs_dst[(size_t)i * (LL * DIM) + (size_t)l * DIM + c] = y;
        acc += y;
    }
    atomicAdd(&out[(size_t)curg * (LL * DIM) + l * DIM + c], acc);
}

__global__ void k_copy_xs(float* __restrict__ dst, long long count) {
    long long t = (long long)blockIdx.x * blockDim.x + threadIdx.x;
    if (t < count) dst[t] = g_xs[t];
}

// ---------------- launch (kernel launches ONLY) ----------------
extern "C" void kernel_launch(void* const* d_in, const int* in_sizes, int n_in,
                              void* d_out, int out_size) {
    const float* x     = (const float*)d_in[0];
    const int*   ei    = (const int*)d_in[1];
    const float* ew    = (const float*)d_in[2];
    const int*   batch = (const int*)d_in[3];
    const float* fc_w  = (const float*)d_in[4];
    const float* W     = (const float*)d_in[5];
    const float* b     = (const float*)d_in[6];
    const float* gamma = (const float*)d_in[7];
    const float* beta  = (const float*)d_in[8];

    float* out = (float*)d_out;

    const long long pool_elems = (long long)GG * LL * DIM;
    const long long xs_elems   = (long long)NN * LL * DIM;
    long long rem = (long long)out_size - pool_elems;
    bool pool_ok = ((long long)out_size >= pool_elems);
    bool direct  = (rem >= xs_elems);
    float* xs_out_tail = out + pool_elems;

    const int T = 256;
    int nb_N  = (NN + T - 1) / T;
    int nb_E  = (EE + T - 1) / T;
    int nb_G  = (NN + 63) / 64;
    int nb_GA = (NN + 15) / 16;
    int nb_AP = (NN + APCH - 1) / APCH;

    // prep (k_init also zeroes the pooled-output region)
    k_init<<<nb_N, T>>>(out, pool_ok ? pool_elems : 0);
    k_deg<<<nb_E, T>>>(ei, ew);
    k_scan_blk<<<NBLK, SCAN_B>>>();
    k_scan_mid<<<1, 32>>>();
    k_scan_add<<<nb_N, T>>>();
    k_fill<<<nb_E, T>>>(ei, ew);

    // h0 = x @ fc_w^T -> g_A (no affine)
    k_gemm_tc<<<nb_G, 128>>>(x, fc_w, gamma, beta, 0, -1, NN);

    for (int l = 0; l < LL; ++l) {
        // hl = A' @ W[l]^T -> g_B (A' = BN-affine using layer l-1 stats for l>=1)
        k_gemm_tc<<<nb_G, 128>>>(nullptr, W + (size_t)l * DIM * DIM,
                                 gamma + (size_t)(l > 0 ? l - 1 : 0) * DIM,
                                 beta + (size_t)(l > 0 ? l - 1 : 0) * DIM,
                                 1, l - 1, NN);
        k_gather<<<nb_GA, 512>>>(b + (size_t)l * DIM, l);
        if (pool_ok) {
            if (direct)
                k_apply_pool<<<nb_AP, 128>>>(batch, xs_out_tail, out,
                                             gamma + (size_t)l * DIM, beta + (size_t)l * DIM, l);
            else
                k_apply_pool<<<nb_AP, 128>>>(batch, g_xs, out,
                                             gamma + (size_t)l * DIM, beta + (size_t)l * DIM, l);
        }
    }

    if (!direct && rem > 0) {
        long long cnt = rem < xs_elems ? rem : xs_elems;
        int nb_CP = (int)((cnt + T - 1) / T);
        k_copy_xs<<<nb_CP, T>>>(out + pool_elems, cnt);
    }
}